// round 13
// baseline (speedup 1.0000x reference)
#include <cuda_runtime.h>
#include <stdint.h>
#include <math.h>

#define BATCH 8192
#define FEAT  128
#define NROWS (2 * BATCH)
#define MARGINF 0.3f
#define NUM_IDS 1000
#define LISTCAP 64
#define W_D2 2.5f
#define NSTRIP 8           // strips of 8 n-tiles
#define STRIPW 8

typedef unsigned long long u64;

// ---------------- device scratch ----------------
__device__ float g_sq[NROWS];
__device__ int   g_maxbits;               // max |x| as float bits
__device__ char  g_q[(size_t)NROWS * FEAT];
__device__ u64  g_rowmin[BATCH][NSTRIP];
__device__ u64  g_colmin[BATCH][64];
__device__ int  g_cnt[2][NUM_IDS];
__device__ int  g_list[2][NUM_IDS][LISTCAP];
__device__ float    g_loss_sum;
__device__ int      g_correct;
__device__ unsigned g_ticket;

// ---------------- helpers ----------------
__device__ __forceinline__ uint32_t sm_u32(const void* p) {
    uint32_t a;
    asm("{ .reg .u64 t; cvta.to.shared.u64 t, %1; cvt.u32.u64 %0, t; }"
        : "=r"(a) : "l"(p));
    return a;
}
__device__ __forceinline__ void cp_async16(uint32_t dst, const void* src) {
    asm volatile("cp.async.cg.shared.global [%0], [%1], 16;"
                 :: "r"(dst), "l"(src));
}
__device__ __forceinline__ void ldsm_x4(uint32_t& r0, uint32_t& r1,
                                        uint32_t& r2, uint32_t& r3, uint32_t a) {
    asm volatile("ldmatrix.sync.aligned.m8n8.x4.shared.b16 {%0,%1,%2,%3}, [%4];"
                 : "=r"(r0), "=r"(r1), "=r"(r2), "=r"(r3) : "r"(a));
}
// int8 mma: byte-level fragment layout identical to m16n8k16.f16
__device__ __forceinline__ void mma_s8(int* d, const uint32_t* a,
                                       const uint32_t* b) {
    asm volatile(
        "mma.sync.aligned.m16n8k32.row.col.s32.s8.s8.s32 "
        "{%0,%1,%2,%3}, {%4,%5,%6,%7}, {%8,%9}, {%0,%1,%2,%3};"
        : "+r"(d[0]), "+r"(d[1]), "+r"(d[2]), "+r"(d[3])
        : "r"(a[0]), "r"(a[1]), "r"(a[2]), "r"(a[3]), "r"(b[0]), "r"(b[1]));
}

#define ROW_B    80
#define STAGE_B  (128 * ROW_B)           // 10240 (64B payload + pad per row)
#define NRING    6
#define OFF_A    0                        // 2 fixed A k-slabs (K=64 s8 each)
#define OFF_B    (2 * STAGE_B)            // 6-slot B ring
#define OFF_MISC (8 * STAGE_B)            // 81920
// misc: t0[128] sqm[128] t1[8][128] sqn[8][128] cmin u64[128] rmin u64[128]
#define SMEM_TOTAL (OFF_MISC + 512 + 512 + 4096 + 4096 + 1024 + 1024)  // 93184

// ---------------------------------------------------------------------------
// Kernel A: squared norms + global max|x| + zero counters/accumulators
// ---------------------------------------------------------------------------
__global__ void prep_kernel(const float* __restrict__ inp) {
    int row  = blockIdx.x * 8 + (threadIdx.x >> 5);
    int lane = threadIdx.x & 31;
    float4 v = reinterpret_cast<const float4*>(inp + (size_t)row * FEAT)[lane];
    float s = v.x * v.x + v.y * v.y + v.z * v.z + v.w * v.w;
    float mx = fmaxf(fmaxf(fabsf(v.x), fabsf(v.y)), fmaxf(fabsf(v.z), fabsf(v.w)));
#pragma unroll
    for (int o = 16; o; o >>= 1) {
        s  += __shfl_down_sync(0xffffffffu, s, o);
        mx  = fmaxf(mx, __shfl_down_sync(0xffffffffu, mx, o));
    }
    if (lane == 0) {
        g_sq[row] = s;
        atomicMax(&g_maxbits, __float_as_int(mx));   // mx >= 0: int order ok
    }

    int idx = blockIdx.x * blockDim.x + threadIdx.x;
    if (idx < 2 * NUM_IDS) reinterpret_cast<int*>(g_cnt)[idx] = 0;
    if (idx == 0) {
        g_loss_sum = 0.f;
        g_correct  = 0;
        g_ticket   = 0u;
    }
}

// zero g_maxbits BEFORE prep (deterministic across graph replays)
__global__ void zero_kernel() {
    if (threadIdx.x == 0 && blockIdx.x == 0) g_maxbits = 0;
}

// ---------------------------------------------------------------------------
// Kernel A2: int8 quantization (after prep: needs global max)
// ---------------------------------------------------------------------------
__global__ void quant_kernel(const float* __restrict__ inp) {
    int row  = blockIdx.x * 8 + (threadIdx.x >> 5);
    int lane = threadIdx.x & 31;
    const float maxv = __int_as_float(g_maxbits);
    const float s = 127.f / maxv;
    float4 v = reinterpret_cast<const float4*>(inp + (size_t)row * FEAT)[lane];
    int q0 = __float2int_rn(v.x * s);
    int q1 = __float2int_rn(v.y * s);
    int q2 = __float2int_rn(v.z * s);
    int q3 = __float2int_rn(v.w * s);
    q0 = max(-127, min(127, q0));  q1 = max(-127, min(127, q1));
    q2 = max(-127, min(127, q2));  q3 = max(-127, min(127, q3));
    uint32_t packed = (uint32_t)(q0 & 0xFF) | ((uint32_t)(q1 & 0xFF) << 8) |
                      ((uint32_t)(q2 & 0xFF) << 16) | ((uint32_t)(q3 & 0xFF) << 24);
    reinterpret_cast<uint32_t*>(g_q + (size_t)row * FEAT)[lane] = packed;
}

__global__ void list_kernel(const int* __restrict__ T) {
    int i = blockIdx.x * blockDim.x + threadIdx.x;
    if (i >= NROWS) return;
    int t = T[i];
    int mod = (i >= BATCH) ? 1 : 0;
    int slot = atomicAdd(&g_cnt[mod][t], 1);
    if (slot < LISTCAP) g_list[mod][t][slot] = i;
}

// ---------------------------------------------------------------------------
// Kernel B: strip-mined int8 approx distance GEMM (negatives argmin mining).
// Same proven pipeline; s8 fragments byte-identical to bf16 ldsm path.
// Units per strip: 16 (8 n-tiles x 2 K-slabs of 64 s8).
// ---------------------------------------------------------------------------
__global__ __launch_bounds__(256, 2) void dist1_kernel(const int* __restrict__ T) {
    extern __shared__ __align__(16) char sm[];
    int*   s_t0   = reinterpret_cast<int*>(sm + OFF_MISC);
    float* s_sqm  = reinterpret_cast<float*>(sm + OFF_MISC + 512);
    int*   s_t1   = reinterpret_cast<int*>(sm + OFF_MISC + 1024);    // [8][128]
    float* s_sqn  = reinterpret_cast<float*>(sm + OFF_MISC + 5120);  // [8][128]
    u64*   s_cmin = reinterpret_cast<u64*>(sm + OFF_MISC + 9216);
    u64*   s_rmin = reinterpret_cast<u64*>(sm + OFF_MISC + 10240);

    const int tid  = threadIdx.x;
    const int lane = tid & 31;
    const int warp = tid >> 5;
    const int wm   = warp >> 2;
    const int wn   = warp & 3;
    const int m0   = blockIdx.y * 128;
    const int nb0  = blockIdx.x * STRIPW;

    if (tid < 128) {
        s_t0[tid]  = T[m0 + tid];
        s_sqm[tid] = g_sq[m0 + tid];
        s_rmin[tid] = ~0ull;
        s_cmin[tid] = ~0ull;
#pragma unroll
        for (int nt = 0; nt < STRIPW; nt++) {
            int n0 = (nb0 + nt) * 128;
            s_t1[nt * 128 + tid]  = T[BATCH + n0 + tid];
            s_sqn[nt * 128 + tid] = g_sq[BATCH + n0 + tid];
        }
    }

    const float maxv = __int_as_float(g_maxbits);
    const float neg2_inv_s2 = -2.f * (maxv * maxv) / (127.f * 127.f);

    const uint32_t smA = sm_u32(sm) + OFF_A;
    const uint32_t smB = sm_u32(sm) + OFF_B;

    const int ld_r0 = tid >> 2;          // rows tid/4, tid/4+64
    const int ld_c  = tid & 3;           // 16B chunk within 64B K-slab
    const uint32_t dA0 = smA + ld_r0 * ROW_B + ld_c * 16;
    const uint32_t dA1 = smA + (ld_r0 + 64) * ROW_B + ld_c * 16;
    const uint32_t dB0 = smB + ld_r0 * ROW_B + ld_c * 16;
    const uint32_t dB1 = smB + (ld_r0 + 64) * ROW_B + ld_c * 16;
    const size_t g0 = (size_t)ld_r0 * FEAT + ld_c * 16;        // byte offsets (s8)
    const size_t g1 = (size_t)(ld_r0 + 64) * FEAT + ld_c * 16;

    const int a_row = wm * 64 + (lane & 15);
    const int a_kh  = lane >> 4;
    const uint32_t aA = smA + a_row * ROW_B + a_kh * 16;
    const int bq  = lane >> 3;
    const int b_c = bq & 1;
    uint32_t aB[2];
#pragma unroll
    for (int j = 0; j < 2; j++) {
        int n_row = wn * 32 + (2 * j + (bq >> 1)) * 8 + (lane & 7);
        aB[j] = smB + n_row * ROW_B + b_c * 16;
    }

    const char* baseA = g_q + (size_t)m0 * FEAT;

    auto issueB = [&](int u) {
        int n0 = (nb0 + (u >> 1)) * 128;
        const char* Bs = g_q + (size_t)(BATCH + n0) * FEAT + (u & 1) * 64;
        const uint32_t so = (uint32_t)(u % NRING) * STAGE_B;
        cp_async16(dB0 + so, Bs + g0);
        cp_async16(dB1 + so, Bs + g1);
    };

    // prologue: A (2 slabs, group 0), then B0..B4 (groups 1..5)
#pragma unroll
    for (int p = 0; p < 2; p++) {
        const char* As = baseA + p * 64;
        const uint32_t so = (uint32_t)p * STAGE_B;
        cp_async16(dA0 + so, As + g0);
        cp_async16(dA1 + so, As + g1);
    }
    asm volatile("cp.async.commit_group;");
#pragma unroll
    for (int u = 0; u < NRING - 1; u++) {
        issueB(u);
        asm volatile("cp.async.commit_group;");
    }

    __syncthreads();   // shared-init writes visible before fragment setup reads

    int m_loc[8], n_base[8];
    float sqm_r[8];
    int   tm_r[8];
#pragma unroll
    for (int mi = 0; mi < 4; mi++)
#pragma unroll
        for (int h = 0; h < 2; h++) {
            int ml = wm * 64 + mi * 16 + (lane >> 2) + 8 * h;
            m_loc[mi * 2 + h] = ml;
            sqm_r[mi * 2 + h] = s_sqm[ml];
            tm_r[mi * 2 + h]  = s_t0[ml];
        }
#pragma unroll
    for (int ni = 0; ni < 4; ni++)
#pragma unroll
        for (int e = 0; e < 2; e++)
            n_base[ni * 2 + e] = wn * 32 + ni * 8 + 2 * (lane & 3) + e;

    u64 rowp[8];
#pragma unroll
    for (int i = 0; i < 8; i++) rowp[i] = ~0ull;

    int acc[4][4][4];
#pragma unroll
    for (int mi = 0; mi < 4; mi++)
#pragma unroll
        for (int ni = 0; ni < 4; ni++)
#pragma unroll
            for (int e = 0; e < 4; e++) acc[mi][ni][e] = 0;

#pragma unroll
    for (int u = 0; u < 2 * STRIPW; u++) {
        // group for B_u = index u+1; wait_group 4 completes it
        asm volatile("cp.async.wait_group 4;");
        __syncthreads();

        if (u + NRING - 1 < 2 * STRIPW) issueB(u + NRING - 1);
        asm volatile("cp.async.commit_group;");

        const uint32_t soA = (uint32_t)(u & 1) * STAGE_B;      // A k-slab
        const uint32_t soB = (uint32_t)(u % NRING) * STAGE_B;  // B ring slot
#pragma unroll
        for (int ks = 0; ks < 2; ks++) {
            uint32_t a[4][4], b[4][2];
#pragma unroll
            for (int mi = 0; mi < 4; mi++)
                ldsm_x4(a[mi][0], a[mi][1], a[mi][2], a[mi][3],
                        aA + soA + mi * (16 * ROW_B) + ks * 32);
#pragma unroll
            for (int j = 0; j < 2; j++) {
                uint32_t r0, r1, r2, r3;
                ldsm_x4(r0, r1, r2, r3, aB[j] + soB + ks * 32);
                b[2 * j + 0][0] = r0;  b[2 * j + 0][1] = r1;
                b[2 * j + 1][0] = r2;  b[2 * j + 1][1] = r3;
            }
#pragma unroll
            for (int mi = 0; mi < 4; mi++)
#pragma unroll
                for (int ni = 0; ni < 4; ni++)
                    mma_s8(acc[mi][ni], a[mi], b[ni]);
        }

        // ---- n-tile epilogue every 2nd unit ----
        if ((u & 1) == 1) {
            const int nt = u >> 1;
            const int n0 = (nb0 + nt) * 128;
            u64 colp[8];
            float sqn_r[8];
            int   tn_r[8];
#pragma unroll
            for (int i = 0; i < 8; i++) {
                colp[i]  = ~0ull;
                sqn_r[i] = s_sqn[nt * 128 + n_base[i]];
                tn_r[i]  = s_t1[nt * 128 + n_base[i]];
            }
#pragma unroll
            for (int mi = 0; mi < 4; mi++)
#pragma unroll
                for (int ni = 0; ni < 4; ni++)
#pragma unroll
                    for (int h = 0; h < 2; h++)
#pragma unroll
                        for (int e = 0; e < 2; e++) {
                            int ri = mi * 2 + h, ci = ni * 2 + e;
                            if (tm_r[ri] != tn_r[ci]) {
                                float d2 = fmaxf(fmaf(neg2_inv_s2,
                                                      __int2float_rn(acc[mi][ni][h * 2 + e]),
                                                      sqm_r[ri] + sqn_r[ci]), 0.f);
                                u64 hi = (u64)__float_as_uint(d2) << 32;
                                u64 pr = hi | (uint32_t)(BATCH + n0 + n_base[ci]);
                                u64 pc = hi | (uint32_t)(m0 + m_loc[ri]);
                                if (pr < rowp[ri]) rowp[ri] = pr;
                                if (pc < colp[ci]) colp[ci] = pc;
                            }
                            acc[mi][ni][h * 2 + e] = 0;   // reset for next tile
                        }
#pragma unroll
            for (int i = 0; i < 8; i++) {
                u64 c = colp[i];
                u64 c4  = __shfl_xor_sync(0xffffffffu, c, 4);   if (c4  < c) c = c4;
                u64 c8  = __shfl_xor_sync(0xffffffffu, c, 8);   if (c8  < c) c = c8;
                u64 c16 = __shfl_xor_sync(0xffffffffu, c, 16);  if (c16 < c) c = c16;
                colp[i] = c;
            }
            if (lane < 4) {
#pragma unroll
                for (int i = 0; i < 8; i++) atomicMin(&s_cmin[n_base[i]], colp[i]);
            }
            __syncthreads();
            if (tid < 128) {
                g_colmin[n0 + tid][blockIdx.y] = s_cmin[tid];
                s_cmin[tid] = ~0ull;
            }
        }
    }

    // ---- strip end: row mins ----
#pragma unroll
    for (int i = 0; i < 8; i++) {
        u64 v = rowp[i];
        u64 w1 = __shfl_xor_sync(0xffffffffu, v, 1);  if (w1 < v) v = w1;
        u64 w2 = __shfl_xor_sync(0xffffffffu, v, 2);  if (w2 < v) v = w2;
        rowp[i] = v;
    }
    if ((lane & 3) == 0) {
#pragma unroll
        for (int i = 0; i < 8; i++) atomicMin(&s_rmin[m_loc[i]], rowp[i]);
    }
    __syncthreads();
    if (tid < 128) g_rowmin[m0 + tid][blockIdx.x] = s_rmin[tid];
}

// ---------------------------------------------------------------------------
// Kernel C: exact refinement + fused final reduction
// ---------------------------------------------------------------------------
__global__ __launch_bounds__(256) void refine_kernel(const float* __restrict__ X,
                                                     const int* __restrict__ T,
                                                     float* __restrict__ out,
                                                     unsigned nblocks) {
    __shared__ float s_loss[8];
    __shared__ int   s_corr[8];
    __shared__ bool  s_last;

    const int wid  = (blockIdx.x * blockDim.x + threadIdx.x) >> 5;
    const int lane = threadIdx.x & 31;
    const int wlocal = (threadIdx.x >> 5);

    u64 e0, e1;
    if (wid < BATCH) {
        e0 = (lane < NSTRIP) ? g_rowmin[wid][lane] : ~0ull;
        e1 = ~0ull;
    } else {
        e0 = g_colmin[wid - BATCH][lane];
        e1 = g_colmin[wid - BATCH][lane + 32];
    }
    u64 m = (e0 < e1) ? e0 : e1;
#pragma unroll
    for (int k = 16; k; k >>= 1) {
        u64 o = __shfl_xor_sync(0xffffffffu, m, k);
        if (o < m) m = o;
    }
    const float thr = __uint_as_float((uint32_t)(m >> 32)) + W_D2;

    const float4 xr  = reinterpret_cast<const float4*>(X)[(size_t)wid * 32 + lane];
    const float  sqi = g_sq[wid];

    float an = __int_as_float(0x7f800000);
    unsigned b0 = __ballot_sync(0xffffffffu,
                                __uint_as_float((uint32_t)(e0 >> 32)) <= thr);
    unsigned b1 = __ballot_sync(0xffffffffu,
                                __uint_as_float((uint32_t)(e1 >> 32)) <= thr);

    auto exact_d2 = [&](int j) -> float {
        float4 yr = reinterpret_cast<const float4*>(X)[(size_t)j * 32 + lane];
        float s = xr.x * yr.x + xr.y * yr.y + xr.z * yr.z + xr.w * yr.w;
#pragma unroll
        for (int k = 16; k; k >>= 1) s += __shfl_xor_sync(0xffffffffu, s, k);
        return fmaxf(fmaf(-2.f, s, sqi + g_sq[j]), 0.f);
    };

    while (b0) {
        int src = __ffs(b0) - 1;  b0 &= b0 - 1;
        u64 e = __shfl_sync(0xffffffffu, e0, src);
        an = fminf(an, exact_d2((int)(uint32_t)e));
    }
    while (b1) {
        int src = __ffs(b1) - 1;  b1 &= b1 - 1;
        u64 e = __shfl_sync(0xffffffffu, e1, src);
        an = fminf(an, exact_d2((int)(uint32_t)e));
    }

    const int t  = T[wid];
    const int om = (wid < BATCH) ? 1 : 0;
    int cnt = g_cnt[om][t];
    if (cnt > LISTCAP) cnt = LISTCAP;
    float ap = 0.f;
    for (int p = 0; p < cnt; p++) {
        int j = g_list[om][t][p];
        ap = fmaxf(ap, exact_d2(j));
    }

    if (lane == 0) {
        float aps = sqrtf(fmaxf(ap, 1e-12f));
        float ans = sqrtf(fmaxf(an, 1e-12f));
        s_loss[wlocal] = fmaxf(aps - ans + MARGINF, 0.f);
        s_corr[wlocal] = (ans >= aps) ? 1 : 0;
    }
    __syncthreads();

    if (threadIdx.x == 0) {
        float ls = 0.f;
        int   cs = 0;
#pragma unroll
        for (int i = 0; i < 8; i++) { ls += s_loss[i]; cs += s_corr[i]; }
        atomicAdd(&g_loss_sum, ls);
        atomicAdd(&g_correct, cs);
        __threadfence();
        unsigned ticket = atomicAdd(&g_ticket, 1u);
        s_last = (ticket == nblocks - 1u);
    }
    __syncthreads();

    if (s_last && threadIdx.x == 0) {
        out[0] = g_loss_sum / (float)NROWS;
        out[1] = (float)g_correct;
        g_ticket = 0u;
    }
}

extern "C" void kernel_launch(void* const* d_in, const int* in_sizes, int n_in,
                              void* d_out, int out_size) {
    const float* X = (const float*)d_in[0];
    const int*   T = (const int*)d_in[1];
    float* out = (float*)d_out;

    static bool attr_set = false;
    if (!attr_set) {
        cudaFuncSetAttribute(dist1_kernel,
                             cudaFuncAttributeMaxDynamicSharedMemorySize, SMEM_TOTAL);
        attr_set = true;
    }

    zero_kernel<<<1, 32>>>();
    prep_kernel<<<NROWS / 8, 256>>>(X);
    quant_kernel<<<NROWS / 8, 256>>>(X);
    list_kernel<<<NROWS / 256, 256>>>(T);
    dist1_kernel<<<dim3(NSTRIP, BATCH / 128), 256, SMEM_TOTAL>>>(T);
    refine_kernel<<<NROWS / 8, 256>>>(X, T, out, NROWS / 8);
}

// round 14
// speedup vs baseline: 1.9965x; 1.9965x over previous
#include <cuda_runtime.h>
#include <cuda_bf16.h>
#include <stdint.h>
#include <math.h>

#define BATCH 8192
#define FEAT  128
#define NROWS (2 * BATCH)
#define MARGINF 0.3f
#define NUM_IDS 1000
#define LISTCAP 64
#define W_D2 1.0f
#define NSTRIP 16          // strips of 4 n-tiles
#define STRIPW 4

typedef unsigned long long u64;

// ---------------- device scratch ----------------
__device__ float g_sq[NROWS];
__device__ __nv_bfloat16 g_hi[(size_t)NROWS * FEAT];
__device__ u64  g_rowmin[BATCH][NSTRIP];  // per (mod0-row, strip)
__device__ u64  g_colmin[BATCH][64];      // per (mod1-row, m-tile)
__device__ int  g_cnt[2][NUM_IDS];
__device__ int  g_list[2][NUM_IDS][LISTCAP];
__device__ float    g_loss_sum;
__device__ int      g_correct;
__device__ unsigned g_ticket;

// ---------------- helpers ----------------
__device__ __forceinline__ uint32_t sm_u32(const void* p) {
    uint32_t a;
    asm("{ .reg .u64 t; cvta.to.shared.u64 t, %1; cvt.u32.u64 %0, t; }"
        : "=r"(a) : "l"(p));
    return a;
}
__device__ __forceinline__ void cp_async16(uint32_t dst, const void* src) {
    asm volatile("cp.async.cg.shared.global [%0], [%1], 16;"
                 :: "r"(dst), "l"(src));
}
__device__ __forceinline__ void ldsm_x4(uint32_t& r0, uint32_t& r1,
                                        uint32_t& r2, uint32_t& r3, uint32_t a) {
    asm volatile("ldmatrix.sync.aligned.m8n8.x4.shared.b16 {%0,%1,%2,%3}, [%4];"
                 : "=r"(r0), "=r"(r1), "=r"(r2), "=r"(r3) : "r"(a));
}
__device__ __forceinline__ void mma_bf16(float* d, const uint32_t* a,
                                         const uint32_t* b) {
    asm volatile(
        "mma.sync.aligned.m16n8k16.row.col.f32.bf16.bf16.f32 "
        "{%0,%1,%2,%3}, {%4,%5,%6,%7}, {%8,%9}, {%0,%1,%2,%3};"
        : "+f"(d[0]), "+f"(d[1]), "+f"(d[2]), "+f"(d[3])
        : "r"(a[0]), "r"(a[1]), "r"(a[2]), "r"(a[3]), "r"(b[0]), "r"(b[1]));
}

#define ROW_B    80
#define STAGE_B  (128 * ROW_B)           // 10240
#define NRING    6
#define OFF_A    0                        // 4 fixed A k-slabs: 40960
#define OFF_B    (4 * STAGE_B)            // 6-slot B ring: 61440
#define OFF_MISC ((4 + NRING) * STAGE_B)  // 102400
// misc: t0[128] sqm[128] t1[4][128] sqn[4][128] cmin u64[128] rmin u64[128]
#define SMEM_TOTAL (OFF_MISC + 512 + 512 + 2048 + 2048 + 1024 + 1024)  // 109568

// ---------------------------------------------------------------------------
// Kernel Z: zero label counters + global accumulators (before prep's atomics)
// ---------------------------------------------------------------------------
__global__ void zero_kernel() {
    for (int i = threadIdx.x; i < 2 * NUM_IDS; i += blockDim.x)
        reinterpret_cast<int*>(g_cnt)[i] = 0;
    if (threadIdx.x == 0) {
        g_loss_sum = 0.f;
        g_correct  = 0;
        g_ticket   = 0u;
    }
}

// ---------------------------------------------------------------------------
// Kernel A: squared norms + bf16 + FUSED per-label list build
// ---------------------------------------------------------------------------
__global__ void prep_kernel(const float* __restrict__ inp,
                            const int* __restrict__ T) {
    int row  = blockIdx.x * 8 + (threadIdx.x >> 5);
    int lane = threadIdx.x & 31;
    float4 v = reinterpret_cast<const float4*>(inp + (size_t)row * FEAT)[lane];
    float s = v.x * v.x + v.y * v.y + v.z * v.z + v.w * v.w;
#pragma unroll
    for (int o = 16; o; o >>= 1) s += __shfl_down_sync(0xffffffffu, s, o);
    if (lane == 0) g_sq[row] = s;

    __nv_bfloat162* ph = reinterpret_cast<__nv_bfloat162*>(g_hi + (size_t)row * FEAT);
    ph[lane * 2 + 0] = __nv_bfloat162(__float2bfloat16(v.x), __float2bfloat16(v.y));
    ph[lane * 2 + 1] = __nv_bfloat162(__float2bfloat16(v.z), __float2bfloat16(v.w));

    // fused list build (g_cnt pre-zeroed by zero_kernel)
    int idx = blockIdx.x * blockDim.x + threadIdx.x;
    if (idx < NROWS) {
        int t = T[idx];
        int mod = (idx >= BATCH) ? 1 : 0;
        int slot = atomicAdd(&g_cnt[mod][t], 1);
        if (slot < LISTCAP) g_list[mod][t][slot] = idx;
    }
}

// ---------------------------------------------------------------------------
// Kernel B: strip-mined approx distance GEMM (negatives argmin mining).
// R12-proven pipeline; NEW epilogue: 7-bit index embedded in d2 mantissa ->
// f32 FMNMX mining (per-element cost 14 -> ~10 ops).
// ---------------------------------------------------------------------------
__global__ __launch_bounds__(256, 2) void dist1_kernel(const int* __restrict__ T) {
    extern __shared__ __align__(16) char sm[];
    int*   s_t0   = reinterpret_cast<int*>(sm + OFF_MISC);
    float* s_sqm  = reinterpret_cast<float*>(sm + OFF_MISC + 512);
    int*   s_t1   = reinterpret_cast<int*>(sm + OFF_MISC + 1024);    // [4][128]
    float* s_sqn  = reinterpret_cast<float*>(sm + OFF_MISC + 3072);  // [4][128]
    u64*   s_cmin = reinterpret_cast<u64*>(sm + OFF_MISC + 5120);
    u64*   s_rmin = reinterpret_cast<u64*>(sm + OFF_MISC + 6144);

    const int tid  = threadIdx.x;
    const int lane = tid & 31;
    const int warp = tid >> 5;
    const int wm   = warp >> 2;
    const int wn   = warp & 3;
    const int m0   = blockIdx.y * 128;
    const int nb0  = blockIdx.x * STRIPW;

    if (tid < 128) {
        s_t0[tid]  = T[m0 + tid];
        s_sqm[tid] = g_sq[m0 + tid];
        s_rmin[tid] = ~0ull;
        s_cmin[tid] = ~0ull;
#pragma unroll
        for (int nt = 0; nt < STRIPW; nt++) {
            int n0 = (nb0 + nt) * 128;
            s_t1[nt * 128 + tid]  = T[BATCH + n0 + tid];
            s_sqn[nt * 128 + tid] = g_sq[BATCH + n0 + tid];
        }
    }

    const uint32_t smA = sm_u32(sm) + OFF_A;
    const uint32_t smB = sm_u32(sm) + OFF_B;

    const int ld_r0 = tid >> 2;
    const int ld_c  = tid & 3;
    const uint32_t dA0 = smA + ld_r0 * ROW_B + ld_c * 16;
    const uint32_t dA1 = smA + (ld_r0 + 64) * ROW_B + ld_c * 16;
    const uint32_t dB0 = smB + ld_r0 * ROW_B + ld_c * 16;
    const uint32_t dB1 = smB + (ld_r0 + 64) * ROW_B + ld_c * 16;
    const size_t g0 = (size_t)ld_r0 * FEAT + ld_c * 8;
    const size_t g1 = (size_t)(ld_r0 + 64) * FEAT + ld_c * 8;

    const int a_row = wm * 64 + (lane & 15);
    const int a_kh  = lane >> 4;
    const uint32_t aA = smA + a_row * ROW_B + a_kh * 16;
    const int bq  = lane >> 3;
    const int b_c = bq & 1;
    uint32_t aB[2];
#pragma unroll
    for (int j = 0; j < 2; j++) {
        int n_row = wn * 32 + (2 * j + (bq >> 1)) * 8 + (lane & 7);
        aB[j] = smB + n_row * ROW_B + b_c * 16;
    }

    const __nv_bfloat16* baseA = g_hi + (size_t)m0 * FEAT;

    auto issueB = [&](int u) {
        int n0 = (nb0 + (u >> 2)) * 128;
        const __nv_bfloat16* Bs = g_hi + (size_t)(BATCH + n0) * FEAT + (u & 3) * 32;
        const uint32_t so = (uint32_t)(u % NRING) * STAGE_B;
        cp_async16(dB0 + so, Bs + g0);
        cp_async16(dB1 + so, Bs + g1);
    };

    // prologue: A (group 0), then B0..B4 (groups 1..5)
#pragma unroll
    for (int p = 0; p < 4; p++) {
        const __nv_bfloat16* As = baseA + p * 32;
        const uint32_t so = (uint32_t)p * STAGE_B;
        cp_async16(dA0 + so, As + g0);
        cp_async16(dA1 + so, As + g1);
    }
    asm volatile("cp.async.commit_group;");
#pragma unroll
    for (int u = 0; u < NRING - 1; u++) {
        issueB(u);
        asm volatile("cp.async.commit_group;");
    }

    __syncthreads();   // shared-init writes visible before fragment setup reads

    int m_loc[8], n_base[8];
    float sqm_r[8];
    int   tm_r[8];
#pragma unroll
    for (int mi = 0; mi < 4; mi++)
#pragma unroll
        for (int h = 0; h < 2; h++) {
            int ml = wm * 64 + mi * 16 + (lane >> 2) + 8 * h;
            m_loc[mi * 2 + h] = ml;
            sqm_r[mi * 2 + h] = s_sqm[ml];
            tm_r[mi * 2 + h]  = s_t0[ml];
        }
#pragma unroll
    for (int ni = 0; ni < 4; ni++)
#pragma unroll
        for (int e = 0; e < 2; e++)
            n_base[ni * 2 + e] = wn * 32 + ni * 8 + 2 * (lane & 3) + e;

    u64 rowp[8];
#pragma unroll
    for (int i = 0; i < 8; i++) rowp[i] = ~0ull;

    float acc[4][4][4];
#pragma unroll
    for (int mi = 0; mi < 4; mi++)
#pragma unroll
        for (int ni = 0; ni < 4; ni++)
#pragma unroll
            for (int e = 0; e < 4; e++) acc[mi][ni][e] = 0.f;

#pragma unroll
    for (int u = 0; u < 16; u++) {
        asm volatile("cp.async.wait_group 4;");
        __syncthreads();

        if (u + NRING - 1 < 16) issueB(u + NRING - 1);
        asm volatile("cp.async.commit_group;");

        const uint32_t soA = (uint32_t)(u & 3) * STAGE_B;      // A k-slab
        const uint32_t soB = (uint32_t)(u % NRING) * STAGE_B;  // B ring slot
#pragma unroll
        for (int ks = 0; ks < 2; ks++) {
            uint32_t a[4][4], b[4][2];
#pragma unroll
            for (int mi = 0; mi < 4; mi++)
                ldsm_x4(a[mi][0], a[mi][1], a[mi][2], a[mi][3],
                        aA + soA + mi * (16 * ROW_B) + ks * 32);
#pragma unroll
            for (int j = 0; j < 2; j++) {
                uint32_t r0, r1, r2, r3;
                ldsm_x4(r0, r1, r2, r3, aB[j] + soB + ks * 32);
                b[2 * j + 0][0] = r0;  b[2 * j + 0][1] = r1;
                b[2 * j + 1][0] = r2;  b[2 * j + 1][1] = r3;
            }
#pragma unroll
            for (int mi = 0; mi < 4; mi++)
#pragma unroll
                for (int ni = 0; ni < 4; ni++)
                    mma_bf16(acc[mi][ni], a[mi], b[ni]);
        }

        // ---- n-tile epilogue every 4th unit: f32 mining w/ embedded index ----
        if ((u & 3) == 3) {
            const int nt = u >> 2;
            const int n0 = (nb0 + nt) * 128;
            float rowf[8], colf[8];
            float sqn_r[8];
            int   tn_r[8];
#pragma unroll
            for (int i = 0; i < 8; i++) {
                rowf[i] = __int_as_float(0x7f800000);
                colf[i] = __int_as_float(0x7f800000);
                sqn_r[i] = s_sqn[nt * 128 + n_base[i]];
                tn_r[i]  = s_t1[nt * 128 + n_base[i]];
            }
#pragma unroll
            for (int mi = 0; mi < 4; mi++)
#pragma unroll
                for (int ni = 0; ni < 4; ni++)
#pragma unroll
                    for (int h = 0; h < 2; h++)
#pragma unroll
                        for (int e = 0; e < 2; e++) {
                            int ri = mi * 2 + h, ci = ni * 2 + e;
                            float d2 = fmaxf(fmaf(-2.f, acc[mi][ni][h * 2 + e],
                                                  sqm_r[ri] + sqn_r[ci]), 0.f);
                            uint32_t db = __float_as_uint(d2) & 0xFFFFFF80u;
                            float vr = __uint_as_float(db | (uint32_t)n_base[ci]);
                            float vc = __uint_as_float(db | (uint32_t)m_loc[ri]);
                            if (tm_r[ri] != tn_r[ci]) {
                                rowf[ri] = fminf(rowf[ri], vr);
                                colf[ci] = fminf(colf[ci], vc);
                            }
                            acc[mi][ni][h * 2 + e] = 0.f;   // reset for next tile
                        }
            // row: convert (d2|col) -> (d2, global col) u64, min into strip acc
#pragma unroll
            for (int i = 0; i < 8; i++) {
                uint32_t rb = __float_as_uint(rowf[i]);
                u64 pr = ((u64)rb << 32) | (uint32_t)(BATCH + n0 + (rb & 127u));
                if (pr < rowp[i]) rowp[i] = pr;
            }
            // col: f32 warp-reduce (xor 4,8,16), then convert + shared atomicMin
#pragma unroll
            for (int i = 0; i < 8; i++) {
                float c = colf[i];
                c = fminf(c, __shfl_xor_sync(0xffffffffu, c, 4));
                c = fminf(c, __shfl_xor_sync(0xffffffffu, c, 8));
                c = fminf(c, __shfl_xor_sync(0xffffffffu, c, 16));
                colf[i] = c;
            }
            if (lane < 4) {
#pragma unroll
                for (int i = 0; i < 8; i++) {
                    uint32_t cb = __float_as_uint(colf[i]);
                    u64 pc = ((u64)cb << 32) | (uint32_t)(m0 + (cb & 127u));
                    atomicMin(&s_cmin[n_base[i]], pc);
                }
            }
            __syncthreads();
            if (tid < 128) {
                g_colmin[n0 + tid][blockIdx.y] = s_cmin[tid];
                s_cmin[tid] = ~0ull;
            }
            // reset ordered before next tile's atomics by next top-of-loop barrier
        }
    }

    // ---- strip end: row mins ----
#pragma unroll
    for (int i = 0; i < 8; i++) {
        u64 v = rowp[i];
        u64 w1 = __shfl_xor_sync(0xffffffffu, v, 1);  if (w1 < v) v = w1;
        u64 w2 = __shfl_xor_sync(0xffffffffu, v, 2);  if (w2 < v) v = w2;
        rowp[i] = v;
    }
    if ((lane & 3) == 0) {
#pragma unroll
        for (int i = 0; i < 8; i++) atomicMin(&s_rmin[m_loc[i]], rowp[i]);
    }
    __syncthreads();
    if (tid < 128) g_rowmin[m0 + tid][blockIdx.x] = s_rmin[tid];
}

// ---------------------------------------------------------------------------
// Kernel C: exact refinement + fused final reduction (R12-proven)
// ---------------------------------------------------------------------------
__global__ __launch_bounds__(256) void refine_kernel(const float* __restrict__ X,
                                                     const int* __restrict__ T,
                                                     float* __restrict__ out,
                                                     unsigned nblocks) {
    __shared__ float s_loss[8];
    __shared__ int   s_corr[8];
    __shared__ bool  s_last;

    const int wid  = (blockIdx.x * blockDim.x + threadIdx.x) >> 5;
    const int lane = threadIdx.x & 31;
    const int wlocal = (threadIdx.x >> 5);

    u64 e0, e1;
    if (wid < BATCH) {
        e0 = (lane < NSTRIP) ? g_rowmin[wid][lane] : ~0ull;
        e1 = ~0ull;
    } else {
        e0 = g_colmin[wid - BATCH][lane];
        e1 = g_colmin[wid - BATCH][lane + 32];
    }
    u64 m = (e0 < e1) ? e0 : e1;
#pragma unroll
    for (int k = 16; k; k >>= 1) {
        u64 o = __shfl_xor_sync(0xffffffffu, m, k);
        if (o < m) m = o;
    }
    const float thr = __uint_as_float((uint32_t)(m >> 32)) + W_D2;

    const float4 xr  = reinterpret_cast<const float4*>(X)[(size_t)wid * 32 + lane];
    const float  sqi = g_sq[wid];

    float an = __int_as_float(0x7f800000);
    unsigned b0 = __ballot_sync(0xffffffffu,
                                __uint_as_float((uint32_t)(e0 >> 32)) <= thr);
    unsigned b1 = __ballot_sync(0xffffffffu,
                                __uint_as_float((uint32_t)(e1 >> 32)) <= thr);

    auto exact_d2 = [&](int j) -> float {
        float4 yr = reinterpret_cast<const float4*>(X)[(size_t)j * 32 + lane];
        float s = xr.x * yr.x + xr.y * yr.y + xr.z * yr.z + xr.w * yr.w;
#pragma unroll
        for (int k = 16; k; k >>= 1) s += __shfl_xor_sync(0xffffffffu, s, k);
        return fmaxf(fmaf(-2.f, s, sqi + g_sq[j]), 0.f);
    };

    while (b0) {
        int src = __ffs(b0) - 1;  b0 &= b0 - 1;
        u64 e = __shfl_sync(0xffffffffu, e0, src);
        an = fminf(an, exact_d2((int)(uint32_t)e));
    }
    while (b1) {
        int src = __ffs(b1) - 1;  b1 &= b1 - 1;
        u64 e = __shfl_sync(0xffffffffu, e1, src);
        an = fminf(an, exact_d2((int)(uint32_t)e));
    }

    const int t  = T[wid];
    const int om = (wid < BATCH) ? 1 : 0;
    int cnt = g_cnt[om][t];
    if (cnt > LISTCAP) cnt = LISTCAP;
    float ap = 0.f;
    for (int p = 0; p < cnt; p++) {
        int j = g_list[om][t][p];
        ap = fmaxf(ap, exact_d2(j));
    }

    if (lane == 0) {
        float aps = sqrtf(fmaxf(ap, 1e-12f));
        float ans = sqrtf(fmaxf(an, 1e-12f));
        s_loss[wlocal] = fmaxf(aps - ans + MARGINF, 0.f);
        s_corr[wlocal] = (ans >= aps) ? 1 : 0;
    }
    __syncthreads();

    if (threadIdx.x == 0) {
        float ls = 0.f;
        int   cs = 0;
#pragma unroll
        for (int i = 0; i < 8; i++) { ls += s_loss[i]; cs += s_corr[i]; }
        atomicAdd(&g_loss_sum, ls);
        atomicAdd(&g_correct, cs);
        __threadfence();
        unsigned ticket = atomicAdd(&g_ticket, 1u);
        s_last = (ticket == nblocks - 1u);
    }
    __syncthreads();

    if (s_last && threadIdx.x == 0) {
        out[0] = g_loss_sum / (float)NROWS;
        out[1] = (float)g_correct;
        g_ticket = 0u;
    }
}

extern "C" void kernel_launch(void* const* d_in, const int* in_sizes, int n_in,
                              void* d_out, int out_size) {
    const float* X = (const float*)d_in[0];
    const int*   T = (const int*)d_in[1];
    float* out = (float*)d_out;

    static bool attr_set = false;
    if (!attr_set) {
        cudaFuncSetAttribute(dist1_kernel,
                             cudaFuncAttributeMaxDynamicSharedMemorySize, SMEM_TOTAL);
        attr_set = true;
    }

    zero_kernel<<<1, 256>>>();
    prep_kernel<<<NROWS / 8, 256>>>(X, T);
    dist1_kernel<<<dim3(NSTRIP, BATCH / 128), 256, SMEM_TOTAL>>>(T);
    refine_kernel<<<NROWS / 8, 256>>>(X, T, out, NROWS / 8);
}